// round 3
// baseline (speedup 1.0000x reference)
#include <cuda_runtime.h>
#include <cstdint>

#define N_Q 16384
#define M_K 4096
#define DD  256
#define YD  7

// ---------------- device scratch (allocation-free rule: __device__ globals) ----
__device__ float g_S[(size_t)N_Q * M_K];   // scores scratch, 268 MB
__device__ float g_W2[M_K * DD];           // fused Wq@YK^T (scale folded), [m][s]
__device__ float g_YV[M_K * DD];           // y@Wv, [m][p]
__device__ float g_T [DD * YD];            // Wq@Wk^T, [s][j]
__device__ float g_pZ[64 * N_Q];           // per-colslice partial sum(exp)
__device__ float g_pR[64 * N_Q];           // per-colslice partial sum(relu)
__device__ float g_cA[N_Q];
__device__ float g_cB[N_Q];

// ---------------- helpers ----------------
__device__ __forceinline__ uint32_t to_tf32(float x) {
    uint32_t u;
    asm("cvt.rna.tf32.f32 %0, %1;" : "=r"(u) : "f"(x));
    return u;
}

__device__ __forceinline__ void mma_tf32(float* c, const uint32_t* a, const uint32_t* b) {
    asm volatile(
        "mma.sync.aligned.m16n8k8.row.col.f32.tf32.tf32.f32 "
        "{%0,%1,%2,%3}, {%4,%5,%6,%7}, {%8,%9}, {%0,%1,%2,%3};"
        : "+f"(c[0]), "+f"(c[1]), "+f"(c[2]), "+f"(c[3])
        : "r"(a[0]), "r"(a[1]), "r"(a[2]), "r"(a[3]),
          "r"(b[0]), "r"(b[1]));
}

// ---------------- k0a: T[s][j] = sum_p Wq[s,p] * Wk[j,p] ----------------
__global__ void k0a(const float* __restrict__ Wq, const float* __restrict__ Wk) {
    __shared__ float wk[DD];
    const int j = blockIdx.x;
    const int tid = threadIdx.x, lane = tid & 31, wid = tid >> 5;
    wk[tid] = Wk[j * DD + tid];
    __syncthreads();
    for (int s0 = 0; s0 < DD; s0 += 8) {
        int s = s0 + wid;
        float sum = 0.f;
        #pragma unroll
        for (int t = 0; t < 8; t++)
            sum += Wq[s * DD + lane + 32 * t] * wk[lane + 32 * t];
        #pragma unroll
        for (int o = 16; o; o >>= 1) sum += __shfl_xor_sync(0xffffffffu, sum, o);
        if (lane == 0) g_T[s * YD + j] = sum;
    }
}

// ---------------- k0b: W2[m][s] = (sum_j T[s][j] y[m][j])/16 ; YV[m][p] ------
__global__ void k0b(const float* __restrict__ y, const float* __restrict__ Wv) {
    const int m = blockIdx.x, p = threadIdx.x;  // p doubles as s
    __shared__ float ys[YD];
    if (p < YD) ys[p] = y[m * YD + p];
    __syncthreads();
    float w2 = 0.f, yv = 0.f;
    #pragma unroll
    for (int j = 0; j < YD; j++) {
        w2 += g_T[p * YD + j] * ys[j];
        yv += ys[j] * Wv[j * DD + p];
    }
    g_W2[m * DD + p] = w2 * 0.0625f;   // scale 1/sqrt(256) folded in
    g_YV[m * DD + p] = yv;
}

// ---------------- k2: S = x @ W2^T  (tf32 mma), + partial Z/R ----------------
// grid (32, 128): 128x128 output tile; 8 warps, warp tile 32x64.
__global__ __launch_bounds__(256) void k2(const float* __restrict__ x) {
    __shared__ uint32_t xs[128 * 36];
    __shared__ uint32_t ws[128 * 36];
    const int tid = threadIdx.x;
    const int qb = blockIdx.y * 128, mb = blockIdx.x * 128;
    const int wid = tid >> 5, lane = tid & 31, g = lane >> 2, tg = lane & 3;
    const int wr = (wid >> 1) * 32, wc = (wid & 1) * 64;

    float acc[2][8][4];
    #pragma unroll
    for (int i = 0; i < 2; i++)
        #pragma unroll
        for (int j = 0; j < 8; j++)
            #pragma unroll
            for (int l = 0; l < 4; l++) acc[i][j][l] = 0.f;

    for (int k0 = 0; k0 < DD; k0 += 32) {
        #pragma unroll
        for (int i = 0; i < 4; i++) {
            int idx = tid + i * 256;
            int r = idx >> 3, c = (idx & 7) * 4;
            float4 vx = *(const float4*)(x + (size_t)(qb + r) * DD + k0 + c);
            uint32_t* d = &xs[r * 36 + c];
            d[0] = to_tf32(vx.x); d[1] = to_tf32(vx.y);
            d[2] = to_tf32(vx.z); d[3] = to_tf32(vx.w);
            float4 vw = *(const float4*)(g_W2 + (size_t)(mb + r) * DD + k0 + c);
            uint32_t* e = &ws[r * 36 + c];
            e[0] = to_tf32(vw.x); e[1] = to_tf32(vw.y);
            e[2] = to_tf32(vw.z); e[3] = to_tf32(vw.w);
        }
        __syncthreads();
        #pragma unroll
        for (int kk = 0; kk < 32; kk += 8) {
            uint32_t a[2][4], b[8][2];
            #pragma unroll
            for (int mt = 0; mt < 2; mt++) {
                int R = wr + mt * 16;
                a[mt][0] = xs[(R + g) * 36 + kk + tg];
                a[mt][1] = xs[(R + 8 + g) * 36 + kk + tg];
                a[mt][2] = xs[(R + g) * 36 + kk + 4 + tg];
                a[mt][3] = xs[(R + 8 + g) * 36 + kk + 4 + tg];
            }
            #pragma unroll
            for (int nt = 0; nt < 8; nt++) {
                int C = wc + nt * 8;
                b[nt][0] = ws[(C + g) * 36 + kk + tg];
                b[nt][1] = ws[(C + g) * 36 + kk + 4 + tg];
            }
            #pragma unroll
            for (int mt = 0; mt < 2; mt++)
                #pragma unroll
                for (int nt = 0; nt < 8; nt++)
                    mma_tf32(acc[mt][nt], a[mt], b[nt]);
        }
        __syncthreads();
    }

    // epilogue: store S, accumulate per-row exp/relu partials
    float es[4] = {0, 0, 0, 0}, rs[4] = {0, 0, 0, 0};
    #pragma unroll
    for (int mt = 0; mt < 2; mt++) {
        #pragma unroll
        for (int h = 0; h < 2; h++) {
            int row = qb + wr + mt * 16 + h * 8 + g;
            #pragma unroll
            for (int nt = 0; nt < 8; nt++) {
                float v0 = acc[mt][nt][h * 2 + 0];
                float v1 = acc[mt][nt][h * 2 + 1];
                int col = mb + wc + nt * 8 + tg * 2;
                *(float2*)(g_S + (size_t)row * M_K + col) = make_float2(v0, v1);
                es[mt * 2 + h] += __expf(v0) + __expf(v1);
                rs[mt * 2 + h] += fmaxf(v0, 0.f) + fmaxf(v1, 0.f);
            }
        }
    }
    #pragma unroll
    for (int i = 0; i < 4; i++) {
        es[i] += __shfl_xor_sync(0xffffffffu, es[i], 1);
        es[i] += __shfl_xor_sync(0xffffffffu, es[i], 2);
        rs[i] += __shfl_xor_sync(0xffffffffu, rs[i], 1);
        rs[i] += __shfl_xor_sync(0xffffffffu, rs[i], 2);
    }
    if (tg == 0) {
        int slice = blockIdx.x * 2 + (wid & 1);
        #pragma unroll
        for (int i = 0; i < 4; i++) {
            int row = qb + wr + (i >> 1) * 16 + (i & 1) * 8 + g;
            g_pZ[slice * N_Q + row] = es[i];
            g_pR[slice * N_Q + row] = rs[i];
        }
    }
}

// ---------------- k2b: reduce partials -> per-row coefficients --------------
__global__ void k2b() {
    int r = blockIdx.x * 256 + threadIdx.x;
    float Z = 0.f, R = 0.f;
    for (int s = 0; s < 64; s++) {
        Z += g_pZ[s * N_Q + r];
        R += g_pR[s * N_Q + r];
    }
    float invDen = 1.f / (0.1f * R + 1.f);
    g_cA[r] = 0.1f * invDen;
    g_cB[r] = invDen / Z;
}

// ---------------- k3: out = P @ YV, P built on the fly ----------------------
// grid (2, 128): 128x128 output tile, K loop over 4096 keys (step 32).
__global__ __launch_bounds__(256) void k3(float* __restrict__ out) {
    __shared__ uint32_t Ps[128 * 36];
    __shared__ uint32_t vs[32 * 136];
    __shared__ float cAs[128], cBs[128];
    const int tid = threadIdx.x;
    const int cb = blockIdx.x * 128, qb = blockIdx.y * 128;
    const int wid = tid >> 5, lane = tid & 31, g = lane >> 2, tg = lane & 3;
    const int wr = (wid >> 1) * 32, wc = (wid & 1) * 64;

    if (tid < 128) { cAs[tid] = g_cA[qb + tid]; cBs[tid] = g_cB[qb + tid]; }
    __syncthreads();

    float acc[2][8][4];
    #pragma unroll
    for (int i = 0; i < 2; i++)
        #pragma unroll
        for (int j = 0; j < 8; j++)
            #pragma unroll
            for (int l = 0; l < 4; l++) acc[i][j][l] = 0.f;

    for (int k0 = 0; k0 < M_K; k0 += 32) {
        #pragma unroll
        for (int i = 0; i < 4; i++) {
            int idx = tid + i * 256;
            {   // P tile: load S, transform, tf32-convert
                int r = idx >> 3, c = (idx & 7) * 4;
                float4 s = *(const float4*)(g_S + (size_t)(qb + r) * M_K + k0 + c);
                float ca = cAs[r], cbb = cBs[r];
                uint32_t* d = &Ps[r * 36 + c];
                d[0] = to_tf32(ca * fmaxf(s.x, 0.f) + cbb * __expf(s.x));
                d[1] = to_tf32(ca * fmaxf(s.y, 0.f) + cbb * __expf(s.y));
                d[2] = to_tf32(ca * fmaxf(s.z, 0.f) + cbb * __expf(s.z));
                d[3] = to_tf32(ca * fmaxf(s.w, 0.f) + cbb * __expf(s.w));
            }
            {   // V tile: [32 keys][128 cols]
                int r = idx >> 5, c = (idx & 31) * 4;
                float4 v = *(const float4*)(g_YV + (size_t)(k0 + r) * DD + cb + c);
                uint32_t* d = &vs[r * 136 + c];
                d[0] = to_tf32(v.x); d[1] = to_tf32(v.y);
                d[2] = to_tf32(v.z); d[3] = to_tf32(v.w);
            }
        }
        __syncthreads();
        #pragma unroll
        for (int kk = 0; kk < 32; kk += 8) {
            uint32_t a[2][4], b[8][2];
            #pragma unroll
            for (int mt = 0; mt < 2; mt++) {
                int R = wr + mt * 16;
                a[mt][0] = Ps[(R + g) * 36 + kk + tg];
                a[mt][1] = Ps[(R + 8 + g) * 36 + kk + tg];
                a[mt][2] = Ps[(R + g) * 36 + kk + 4 + tg];
                a[mt][3] = Ps[(R + 8 + g) * 36 + kk + 4 + tg];
            }
            #pragma unroll
            for (int nt = 0; nt < 8; nt++) {
                int C = wc + nt * 8;
                b[nt][0] = vs[(kk + tg) * 136 + C + g];
                b[nt][1] = vs[(kk + 4 + tg) * 136 + C + g];
            }
            #pragma unroll
            for (int mt = 0; mt < 2; mt++)
                #pragma unroll
                for (int nt = 0; nt < 8; nt++)
                    mma_tf32(acc[mt][nt], a[mt], b[nt]);
        }
        __syncthreads();
    }

    // epilogue: write output (weights already fully normalized)
    #pragma unroll
    for (int mt = 0; mt < 2; mt++) {
        #pragma unroll
        for (int h = 0; h < 2; h++) {
            int row = qb + wr + mt * 16 + h * 8 + g;
            #pragma unroll
            for (int nt = 0; nt < 8; nt++) {
                float v0 = acc[mt][nt][h * 2 + 0];
                float v1 = acc[mt][nt][h * 2 + 1];
                int col = cb + wc + nt * 8 + tg * 2;
                *(float2*)(out + (size_t)row * DD + col) = make_float2(v0, v1);
            }
        }
    }
}

// ---------------- launcher ----------------
extern "C" void kernel_launch(void* const* d_in, const int* in_sizes, int n_in,
                              void* d_out, int out_size) {
    const float* x  = (const float*)d_in[0];   // [16384, 256]
    const float* y  = (const float*)d_in[1];   // [4096, 7]
    const float* Wq = (const float*)d_in[2];   // [256, 256]
    const float* Wk = (const float*)d_in[3];   // [7, 256]
    const float* Wv = (const float*)d_in[4];   // [7, 256]
    float* out = (float*)d_out;                // [16384, 256]

    k0a<<<YD, 256>>>(Wq, Wk);
    k0b<<<M_K, 256>>>(y, Wv);
    k2<<<dim3(M_K / 128, N_Q / 128), 256>>>(x);
    k2b<<<N_Q / 256, 256>>>();
    k3<<<dim3(DD / 128, N_Q / 128), 256>>>(out);
}

// round 7
// speedup vs baseline: 9.3974x; 9.3974x over previous
#include <cuda_runtime.h>
#include <cuda_bf16.h>
#include <cstdint>

#define N_Q 16384
#define M_K 4096
#define DD  256
#define YD  7

// T[s][j] = (Wq @ Wk^T)[s][j] / 16, col 7 = 0
__device__ float g_T[DD * 8];

// ---------------- helpers ----------------
__device__ __forceinline__ uint32_t to_tf32(float x) {
    uint32_t u;
    asm("cvt.rna.tf32.f32 %0, %1;" : "=r"(u) : "f"(x));
    return u;
}
__device__ __forceinline__ uint32_t pack_bf16x2(float lo, float hi) {
    uint32_t r;
    asm("cvt.rn.bf16x2.f32 %0, %1, %2;" : "=r"(r) : "f"(hi), "f"(lo));
    return r;
}
__device__ __forceinline__ void mma_tf32(float* c, const uint32_t* a,
                                         uint32_t b0, uint32_t b1) {
    asm volatile(
        "mma.sync.aligned.m16n8k8.row.col.f32.tf32.tf32.f32 "
        "{%0,%1,%2,%3}, {%4,%5,%6,%7}, {%8,%9}, {%0,%1,%2,%3};"
        : "+f"(c[0]), "+f"(c[1]), "+f"(c[2]), "+f"(c[3])
        : "r"(a[0]), "r"(a[1]), "r"(a[2]), "r"(a[3]), "r"(b0), "r"(b1));
}
__device__ __forceinline__ void mma_bf16(float* c, const uint32_t* a,
                                         uint32_t b0, uint32_t b1) {
    asm volatile(
        "mma.sync.aligned.m16n8k16.row.col.f32.bf16.bf16.f32 "
        "{%0,%1,%2,%3}, {%4,%5,%6,%7}, {%8,%9}, {%0,%1,%2,%3};"
        : "+f"(c[0]), "+f"(c[1]), "+f"(c[2]), "+f"(c[3])
        : "r"(a[0]), "r"(a[1]), "r"(a[2]), "r"(a[3]), "r"(b0), "r"(b1));
}

// ---------------- k0a: T = Wq @ Wk^T / 16, col 7 = 0 ----------------
__global__ void k0a(const float* __restrict__ Wq, const float* __restrict__ Wk) {
    __shared__ float wk[DD];
    const int j = blockIdx.x;
    const int tid = threadIdx.x, lane = tid & 31, wid = tid >> 5;
    if (j == YD) {                 // zero the padding column
        g_T[tid * 8 + YD] = 0.f;
        return;
    }
    wk[tid] = Wk[j * DD + tid];
    __syncthreads();
    for (int s0 = 0; s0 < DD; s0 += 8) {
        int s = s0 + wid;
        float sum = 0.f;
        #pragma unroll
        for (int t = 0; t < 8; t++)
            sum += Wq[s * DD + lane + 32 * t] * wk[lane + 32 * t];
        #pragma unroll
        for (int o = 16; o; o >>= 1) sum += __shfl_xor_sync(0xffffffffu, sum, o);
        if (lane == 0) g_T[s * 8 + j] = sum * 0.0625f;
    }
}

// ---------------- kmain: fused low-rank attention ----------------
// grid = 128 CTAs (128 query rows each), 256 threads (8 warps x 16 rows).
__global__ __launch_bounds__(256) void kmain(
    const float* __restrict__ x, const float* __restrict__ y,
    const float* __restrict__ Wv, float* __restrict__ out)
{
    __shared__ float    Ts[DD][8];            // T
    __shared__ float    Us[128][9];           // U rows (pad 9)
    __shared__ uint32_t ys2[2][128 * 9];      // tf32 y' [key][j], stride 9
    __shared__ uint32_t ysT[2][8][68];        // bf16 y'^T [j][key pairs], stride 68 words
    __shared__ float    Wvs[8][264];          // Wv padded (row 7 = 0)
    __shared__ float    wgt[8][16][8];        // per-warp combine weights

    const int tid = threadIdx.x, w = tid >> 5, lane = tid & 31;
    const int g = lane >> 2, tg = lane & 3;
    const int qb = blockIdx.x * 128;

    // ---- load T and Wv ----
    for (int i = tid; i < DD * 8; i += 256) ((float*)Ts)[i] = g_T[i];
    for (int i = tid; i < 8 * DD; i += 256) {
        int j = i >> 8, c = i & 255;
        Wvs[j][c] = (j < YD) ? Wv[j * DD + c] : 0.f;
    }
    __syncthreads();

    // ---- Phase A: U = x_tile @ T (2 threads per row, split K) ----
    {
        const int r = tid >> 1, h = tid & 1;
        float acc[8];
        #pragma unroll
        for (int j = 0; j < 8; j++) acc[j] = 0.f;
        const float* xr = x + (size_t)(qb + r) * DD + h * 128;
        const float* tb = &Ts[h * 128][0];
        for (int k = 0; k < 128; k += 4) {
            float4 xv = *(const float4*)(xr + k);
            const float* t0 = tb + (k + 0) * 8;
            const float* t1 = tb + (k + 1) * 8;
            const float* t2 = tb + (k + 2) * 8;
            const float* t3 = tb + (k + 3) * 8;
            #pragma unroll
            for (int j = 0; j < 8; j++)
                acc[j] += xv.x * t0[j] + xv.y * t1[j] + xv.z * t2[j] + xv.w * t3[j];
        }
        if (h == 0) {
            #pragma unroll
            for (int j = 0; j < 8; j++) Us[r][j] = acc[j];
        }
        __syncthreads();
        if (h == 1) {
            #pragma unroll
            for (int j = 0; j < 8; j++) Us[r][j] += acc[j];
        }
        __syncthreads();
    }

    // ---- per-warp tf32 A-fragment of U (K=8, persistent) ----
    uint32_t ua[4];
    {
        const int r0 = w * 16 + g;
        ua[0] = to_tf32(Us[r0][tg]);
        ua[1] = to_tf32(Us[r0 + 8][tg]);
        ua[2] = to_tf32(Us[r0][tg + 4]);
        ua[3] = to_tf32(Us[r0 + 8][tg + 4]);
    }

    float eE[4] = {0.f, 0.f, 0.f, 0.f};
    float eG[4] = {0.f, 0.f, 0.f, 0.f};

    // ---- y' tile loader (cooperative, double-buffered) ----
    auto load_ys = [&](int tile, int buf) {
        const int mb = tile * 128;
        #pragma unroll
        for (int ii = 0; ii < 4; ii++) {
            int i = tid + ii * 256;            // 1024 entries
            int r = i >> 3, j = i & 7;
            float v = (j < YD) ? y[(size_t)(mb + r) * YD + j] : 1.0f;
            ys2[buf][r * 9 + j] = to_tf32(v);
            __nv_bfloat16* p = (__nv_bfloat16*)&ysT[buf][j][0];
            p[r] = __float2bfloat16(v);
        }
    };

    load_ys(0, 0);

    // ---- main loop over 32 key tiles ----
    for (int t = 0; t < 32; t++) {
        const int buf = t & 1;
        __syncthreads();                       // buf ready; prev compute done
        if (t < 31) load_ys(t + 1, buf ^ 1);

        const uint32_t* ysb = ys2[buf];
        const uint32_t* yT  = &ysT[buf][0][0];

        #pragma unroll
        for (int kk = 0; kk < 8; kk++) {
            uint32_t ae[4], ag[4];
            #pragma unroll
            for (int half = 0; half < 2; half++) {
                const int nt = kk * 2 + half;
                uint32_t b0 = ysb[(nt * 8 + g) * 9 + tg];
                uint32_t b1 = ysb[(nt * 8 + g) * 9 + tg + 4];
                float c[4] = {0.f, 0.f, 0.f, 0.f};
                mma_tf32(c, ua, b0, b1);
                float e0 = __expf(c[0]), e1 = __expf(c[1]);
                float e2 = __expf(c[2]), e3 = __expf(c[3]);
                float r0 = fmaxf(c[0], 0.f), r1 = fmaxf(c[1], 0.f);
                float r2 = fmaxf(c[2], 0.f), r3 = fmaxf(c[3], 0.f);
                ae[half * 2 + 0] = pack_bf16x2(e0, e1);   // row g,   k=2tg..+1
                ae[half * 2 + 1] = pack_bf16x2(e2, e3);   // row g+8
                ag[half * 2 + 0] = pack_bf16x2(r0, r1);
                ag[half * 2 + 1] = pack_bf16x2(r2, r3);
            }
            uint32_t bb0 = yT[g * 68 + kk * 8 + tg];
            uint32_t bb1 = yT[g * 68 + kk * 8 + tg + 4];
            mma_bf16(eE, ae, bb0, bb1);
            mma_bf16(eG, ag, bb0, bb1);
        }
    }

    // ---- per-row coefficients (Z, R live in column 7 => lane tg==3) ----
    const int src = (lane & ~3) | 3;
    float Z0 = __shfl_sync(0xffffffffu, eE[1], src);
    float Z1 = __shfl_sync(0xffffffffu, eE[3], src);
    float R0 = __shfl_sync(0xffffffffu, eG[1], src);
    float R1 = __shfl_sync(0xffffffffu, eG[3], src);
    float inv0 = 1.f / (0.1f * R0 + 1.f);
    float inv1 = 1.f / (0.1f * R1 + 1.f);
    float cA0 = 0.1f * inv0, cB0 = inv0 / Z0;
    float cA1 = 0.1f * inv1, cB1 = inv1 / Z1;

    wgt[w][g][2 * tg]         = cA0 * eG[0] + cB0 * eE[0];
    wgt[w][g][2 * tg + 1]     = cA0 * eG[1] + cB0 * eE[1];   // col 7 garbage; Wvs row7=0
    wgt[w][g + 8][2 * tg]     = cA1 * eG[2] + cB1 * eE[2];
    wgt[w][g + 8][2 * tg + 1] = cA1 * eG[3] + cB1 * eE[3];
    __syncwarp();

    // ---- out = wgt @ Wv (per warp: 16 rows x 256 cols; lane owns 8 cols) ----
    const int c0 = lane * 8;
    float wv[8][8];
    #pragma unroll
    for (int j = 0; j < 8; j++) {
        float4 v0 = *(const float4*)&Wvs[j][c0];
        float4 v1 = *(const float4*)&Wvs[j][c0 + 4];
        wv[j][0] = v0.x; wv[j][1] = v0.y; wv[j][2] = v0.z; wv[j][3] = v0.w;
        wv[j][4] = v1.x; wv[j][5] = v1.y; wv[j][6] = v1.z; wv[j][7] = v1.w;
    }
    #pragma unroll 4
    for (int row = 0; row < 16; row++) {
        float wj[8];
        #pragma unroll
        for (int j = 0; j < 8; j++) wj[j] = wgt[w][row][j];
        float acc[8];
        #pragma unroll
        for (int c = 0; c < 8; c++) acc[c] = 0.f;
        #pragma unroll
        for (int j = 0; j < 8; j++)
            #pragma unroll
            for (int c = 0; c < 8; c++) acc[c] += wj[j] * wv[j][c];
        float* orow = out + (size_t)(qb + w * 16 + row) * DD + c0;
        *(float4*)(orow)     = make_float4(acc[0], acc[1], acc[2], acc[3]);
        *(float4*)(orow + 4) = make_float4(acc[4], acc[5], acc[6], acc[7]);
    }
}

// ---------------- launcher ----------------
extern "C" void kernel_launch(void* const* d_in, const int* in_sizes, int n_in,
                              void* d_out, int out_size) {
    const float* x  = (const float*)d_in[0];   // [16384, 256]
    const float* y  = (const float*)d_in[1];   // [4096, 7]
    const float* Wq = (const float*)d_in[2];   // [256, 256]
    const float* Wk = (const float*)d_in[3];   // [7, 256]
    const float* Wv = (const float*)d_in[4];   // [7, 256]
    float* out = (float*)d_out;                // [16384, 256]

    k0a<<<8, 256>>>(Wq, Wk);
    kmain<<<N_Q / 128, 256>>>(x, y, Wv, out);
}

// round 8
// speedup vs baseline: 13.2356x; 1.4084x over previous
#include <cuda_runtime.h>
#include <cuda_bf16.h>
#include <cstdint>

#define N_Q 16384
#define M_K 4096
#define DD  256
#define YD  7
#define LOG2E 1.4426950408889634f

// T[s][j] = (Wq @ Wk^T)[s][j] * (log2e/16), col 7 = 0
__device__ float g_T[DD * 8];

// ---------------- helpers ----------------
__device__ __forceinline__ uint32_t to_tf32(float x) {
    uint32_t u;
    asm("cvt.rna.tf32.f32 %0, %1;" : "=r"(u) : "f"(x));
    return u;
}
__device__ __forceinline__ uint32_t pack_bf16x2(float lo, float hi) {
    uint32_t r;
    asm("cvt.rn.bf16x2.f32 %0, %1, %2;" : "=r"(r) : "f"(hi), "f"(lo));
    return r;
}
__device__ __forceinline__ uint32_t bmax0(uint32_t v) {
    uint32_t r;
    asm("max.bf16x2 %0, %1, %2;" : "=r"(r) : "r"(v), "r"(0u));
    return r;
}
__device__ __forceinline__ float ex2f(float x) {
    float r;
    asm("ex2.approx.ftz.f32 %0, %1;" : "=f"(r) : "f"(x));
    return r;
}
__device__ __forceinline__ void mma_tf32(float* c, const uint32_t* a,
                                         uint32_t b0, uint32_t b1) {
    asm volatile(
        "mma.sync.aligned.m16n8k8.row.col.f32.tf32.tf32.f32 "
        "{%0,%1,%2,%3}, {%4,%5,%6,%7}, {%8,%9}, {%0,%1,%2,%3};"
        : "+f"(c[0]), "+f"(c[1]), "+f"(c[2]), "+f"(c[3])
        : "r"(a[0]), "r"(a[1]), "r"(a[2]), "r"(a[3]), "r"(b0), "r"(b1));
}
__device__ __forceinline__ void mma_bf16(float* c, const uint32_t* a,
                                         uint32_t b0, uint32_t b1) {
    asm volatile(
        "mma.sync.aligned.m16n8k16.row.col.f32.bf16.bf16.f32 "
        "{%0,%1,%2,%3}, {%4,%5,%6,%7}, {%8,%9}, {%0,%1,%2,%3};"
        : "+f"(c[0]), "+f"(c[1]), "+f"(c[2]), "+f"(c[3])
        : "r"(a[0]), "r"(a[1]), "r"(a[2]), "r"(a[3]), "r"(b0), "r"(b1));
}

// ---------------- k0a: T = Wq @ Wk^T * (log2e/16), col 7 = 0 ----------------
__global__ void k0a(const float* __restrict__ Wq, const float* __restrict__ Wk) {
    __shared__ float wk[DD];
    const int j = blockIdx.x;
    const int tid = threadIdx.x, lane = tid & 31, wid = tid >> 5;
    if (j == YD) {
        g_T[tid * 8 + YD] = 0.f;
        return;
    }
    wk[tid] = Wk[j * DD + tid];
    __syncthreads();
    for (int s0 = 0; s0 < DD; s0 += 8) {
        int s = s0 + wid;
        float sum = 0.f;
        #pragma unroll
        for (int t = 0; t < 8; t++)
            sum += Wq[s * DD + lane + 32 * t] * wk[lane + 32 * t];
        #pragma unroll
        for (int o = 16; o; o >>= 1) sum += __shfl_xor_sync(0xffffffffu, sum, o);
        if (lane == 0) g_T[s * 8 + j] = sum * (0.0625f * LOG2E);
    }
}

// ---------------- kmain: fused low-rank attention ----------------
// grid = 256 CTAs (64 query rows each), 128 threads (4 warps x 16 rows).
__global__ __launch_bounds__(128) void kmain(
    const float* __restrict__ x, const float* __restrict__ y,
    const float* __restrict__ Wv, float* __restrict__ out)
{
    __shared__ float Ts[DD][8];
    __shared__ float Us[64][9];
    __shared__ __align__(16) uint32_t ys2[2][128 * 10];  // tf32 y', j interleaved [0,4,1,5,2,6,3,7]
    __shared__ __align__(16) uint32_t ysT[2][8 * 66];    // bf16 y'^T, inner-8 interleaved
    __shared__ float Wvs[8][264];                        // Wv padded (row 7 = 0)
    __shared__ float wgt[4][16][8];

    const int tid = threadIdx.x, w = tid >> 5, lane = tid & 31;
    const int g = lane >> 2, tg = lane & 3;
    const int qb = blockIdx.x * 64;

    // ---- load T and Wv ----
    for (int i = tid; i < DD * 8; i += 128) ((float*)Ts)[i] = g_T[i];
    for (int i = tid; i < 8 * DD; i += 128) {
        int j = i >> 8, c = i & 255;
        Wvs[j][c] = (j < YD) ? Wv[j * DD + c] : 0.f;
    }
    __syncthreads();

    // ---- Phase A: U = x_tile @ T (2 threads per row, split K) ----
    {
        const int r = tid >> 1, h = tid & 1;
        float acc[8];
        #pragma unroll
        for (int j = 0; j < 8; j++) acc[j] = 0.f;
        const float* xr = x + (size_t)(qb + r) * DD + h * 128;
        const float* tb = &Ts[h * 128][0];
        for (int k = 0; k < 128; k += 4) {
            float4 xv = *(const float4*)(xr + k);
            const float* t0 = tb + (k + 0) * 8;
            const float* t1 = tb + (k + 1) * 8;
            const float* t2 = tb + (k + 2) * 8;
            const float* t3 = tb + (k + 3) * 8;
            #pragma unroll
            for (int j = 0; j < 8; j++)
                acc[j] += xv.x * t0[j] + xv.y * t1[j] + xv.z * t2[j] + xv.w * t3[j];
        }
        if (h == 0) {
            #pragma unroll
            for (int j = 0; j < 8; j++) Us[r][j] = acc[j];
        }
        __syncthreads();
        if (h == 1) {
            #pragma unroll
            for (int j = 0; j < 8; j++) Us[r][j] += acc[j];
        }
        __syncthreads();
    }

    // ---- per-warp tf32 A-fragment of U (K=8, persistent) ----
    uint32_t ua[4];
    {
        const int r0 = w * 16 + g;
        ua[0] = to_tf32(Us[r0][tg]);
        ua[1] = to_tf32(Us[r0 + 8][tg]);
        ua[2] = to_tf32(Us[r0][tg + 4]);
        ua[3] = to_tf32(Us[r0 + 8][tg + 4]);
    }

    float eE0[4] = {0.f, 0.f, 0.f, 0.f}, eE1[4] = {0.f, 0.f, 0.f, 0.f};
    float eG0[4] = {0.f, 0.f, 0.f, 0.f}, eG1[4] = {0.f, 0.f, 0.f, 0.f};

    // ---- y' tile loader (cooperative, double-buffered) ----
    auto load_ys = [&](int tile, int buf) {
        const int mb = tile * 128;
        #pragma unroll
        for (int ii = 0; ii < 8; ii++) {
            int i = tid + ii * 128;            // 1024 entries
            int r = i >> 3, j = i & 7;
            float v = (j < YD) ? y[(size_t)(mb + r) * YD + j] : 1.0f;
            int jp = 2 * (j & 3) + (j >> 2);               // pair interleave
            ys2[buf][r * 10 + jp] = to_tf32(v);
            uint32_t wi = (uint32_t)(r >> 1);
            uint32_t t8 = wi & 7u;
            uint32_t np = (wi & ~7u) | (2u * (t8 & 3u) + (t8 >> 2));
            __nv_bfloat16* p = (__nv_bfloat16*)&ysT[buf][j * 66 + np];
            p[r & 1] = __float2bfloat16(v);
        }
    };

    load_ys(0, 0);

    // ---- main loop over 32 key tiles ----
    for (int t = 0; t < 32; t++) {
        const int buf = t & 1;
        __syncthreads();
        if (t < 31) load_ys(t + 1, buf ^ 1);

        const uint32_t* ysb = ys2[buf];
        const uint32_t* yT  = ysT[buf];

        #pragma unroll
        for (int kk = 0; kk < 8; kk++) {
            uint32_t ae[4], ag[4];
            #pragma unroll
            for (int half = 0; half < 2; half++) {
                const int nt = kk * 2 + half;
                uint2 bb = *(const uint2*)&ysb[((nt * 8 + g) * 10) + 2 * tg];
                float c[4] = {0.f, 0.f, 0.f, 0.f};
                mma_tf32(c, ua, bb.x, bb.y);         // c = s * log2e
                float e0 = ex2f(c[0]), e1 = ex2f(c[1]);
                float e2 = ex2f(c[2]), e3 = ex2f(c[3]);
                ae[half * 2 + 0] = pack_bf16x2(e0, e1);
                ae[half * 2 + 1] = pack_bf16x2(e2, e3);
                ag[half * 2 + 0] = bmax0(pack_bf16x2(c[0], c[1]));
                ag[half * 2 + 1] = bmax0(pack_bf16x2(c[2], c[3]));
            }
            uint2 vb = *(const uint2*)&yT[g * 66 + kk * 8 + 2 * tg];
            if (kk & 1) {
                mma_bf16(eE1, ae, vb.x, vb.y);
                mma_bf16(eG1, ag, vb.x, vb.y);
            } else {
                mma_bf16(eE0, ae, vb.x, vb.y);
                mma_bf16(eG0, ag, vb.x, vb.y);
            }
        }
    }
    float eE[4], eG[4];
    #pragma unroll
    for (int i = 0; i < 4; i++) { eE[i] = eE0[i] + eE1[i]; eG[i] = eG0[i] + eG1[i]; }

    // ---- per-row coefficients (Z, R_c in column 7 => lane tg==3, reg 1/3) ----
    // scores were scaled by log2e: relu(s) = ln2 * relu(c); R_true = ln2 * R_c
    const int src = (lane & ~3) | 3;
    float Z0 = __shfl_sync(0xffffffffu, eE[1], src);
    float Z1 = __shfl_sync(0xffffffffu, eE[3], src);
    float R0 = __shfl_sync(0xffffffffu, eG[1], src);
    float R1 = __shfl_sync(0xffffffffu, eG[3], src);
    const float LN2_10 = 0.06931471805599453f;       // 0.1 * ln2
    float inv0 = 1.f / (LN2_10 * R0 + 1.f);
    float inv1 = 1.f / (LN2_10 * R1 + 1.f);
    float cA0 = LN2_10 * inv0, cB0 = inv0 / Z0;
    float cA1 = LN2_10 * inv1, cB1 = inv1 / Z1;

    wgt[w][g][2 * tg]         = cA0 * eG[0] + cB0 * eE[0];
    wgt[w][g][2 * tg + 1]     = cA0 * eG[1] + cB0 * eE[1];   // col 7 garbage; Wvs row7=0
    wgt[w][g + 8][2 * tg]     = cA1 * eG[2] + cB1 * eE[2];
    wgt[w][g + 8][2 * tg + 1] = cA1 * eG[3] + cB1 * eE[3];
    __syncwarp();

    // ---- out = wgt @ Wv (per warp: 16 rows x 256 cols; lane owns 8 cols) ----
    const int c0 = lane * 8;
    float wv[8][8];
    #pragma unroll
    for (int j = 0; j < 8; j++) {
        float4 v0 = *(const float4*)&Wvs[j][c0];
        float4 v1 = *(const float4*)&Wvs[j][c0 + 4];
        wv[j][0] = v0.x; wv[j][1] = v0.y; wv[j][2] = v0.z; wv[j][3] = v0.w;
        wv[j][4] = v1.x; wv[j][5] = v1.y; wv[j][6] = v1.z; wv[j][7] = v1.w;
    }
    #pragma unroll 4
    for (int row = 0; row < 16; row++) {
        float wj[8];
        #pragma unroll
        for (int j = 0; j < 8; j++) wj[j] = wgt[w][row][j];
        float acc[8];
        #pragma unroll
        for (int c = 0; c < 8; c++) acc[c] = 0.f;
        #pragma unroll
        for (int j = 0; j < 8; j++)
            #pragma unroll
            for (int c = 0; c < 8; c++) acc[c] += wj[j] * wv[j][c];
        float* orow = out + (size_t)(qb + w * 16 + row) * DD + c0;
        *(float4*)(orow)     = make_float4(acc[0], acc[1], acc[2], acc[3]);
        *(float4*)(orow + 4) = make_float4(acc[4], acc[5], acc[6], acc[7]);
    }
}

// ---------------- launcher ----------------
extern "C" void kernel_launch(void* const* d_in, const int* in_sizes, int n_in,
                              void* d_out, int out_size) {
    const float* x  = (const float*)d_in[0];   // [16384, 256]
    const float* y  = (const float*)d_in[1];   // [4096, 7]
    const float* Wq = (const float*)d_in[2];   // [256, 256]
    const float* Wk = (const float*)d_in[3];   // [7, 256]
    const float* Wv = (const float*)d_in[4];   // [7, 256]
    float* out = (float*)d_out;                // [16384, 256]

    k0a<<<8, 256>>>(Wq, Wk);
    kmain<<<N_Q / 64, 128>>>(x, y, Wv, out);
}

// round 12
// speedup vs baseline: 13.9065x; 1.0507x over previous
#include <cuda_runtime.h>
#include <cuda_bf16.h>
#include <cstdint>

#define N_Q 16384
#define M_K 4096
#define DD  256
#define YD  7
#define LOG2E 1.4426950408889634f

// T[s][j] = (Wq @ Wk^T)[s][j] * (log2e/16), col 7 = 0
__device__ float g_T[DD * 8];

// ---------------- helpers ----------------
__device__ __forceinline__ uint32_t to_tf32(float x) {
    uint32_t u;
    asm("cvt.rna.tf32.f32 %0, %1;" : "=r"(u) : "f"(x));
    return u;
}
__device__ __forceinline__ uint32_t pack_bf16x2(float lo, float hi) {
    uint32_t r;
    asm("cvt.rn.bf16x2.f32 %0, %1, %2;" : "=r"(r) : "f"(hi), "f"(lo));
    return r;
}
__device__ __forceinline__ uint32_t bmax0(uint32_t v) {
    uint32_t r;
    asm("max.bf16x2 %0, %1, %2;" : "=r"(r) : "r"(v), "r"(0u));
    return r;
}
__device__ __forceinline__ float ex2f(float x) {
    float r;
    asm("ex2.approx.ftz.f32 %0, %1;" : "=f"(r) : "f"(x));
    return r;
}
__device__ __forceinline__ void mma_tf32(float* c, const uint32_t* a,
                                         uint32_t b0, uint32_t b1) {
    asm volatile(
        "mma.sync.aligned.m16n8k8.row.col.f32.tf32.tf32.f32 "
        "{%0,%1,%2,%3}, {%4,%5,%6,%7}, {%8,%9}, {%0,%1,%2,%3};"
        : "+f"(c[0]), "+f"(c[1]), "+f"(c[2]), "+f"(c[3])
        : "r"(a[0]), "r"(a[1]), "r"(a[2]), "r"(a[3]), "r"(b0), "r"(b1));
}
__device__ __forceinline__ void mma_bf16(float* c, const uint32_t* a,
                                         uint32_t b0, uint32_t b1) {
    asm volatile(
        "mma.sync.aligned.m16n8k16.row.col.f32.bf16.bf16.f32 "
        "{%0,%1,%2,%3}, {%4,%5,%6,%7}, {%8,%9}, {%0,%1,%2,%3};"
        : "+f"(c[0]), "+f"(c[1]), "+f"(c[2]), "+f"(c[3])
        : "r"(a[0]), "r"(a[1]), "r"(a[2]), "r"(a[3]), "r"(b0), "r"(b1));
}

// ---------------- k0a: T = Wq @ Wk^T * (log2e/16), col 7 = 0 ----------------
// grid (8, 4): j = bx, s-chunk = by (64 rows each)
__global__ void k0a(const float* __restrict__ Wq, const float* __restrict__ Wk) {
    __shared__ float wk[DD];
    const int j = blockIdx.x;
    const int tid = threadIdx.x, lane = tid & 31, wid = tid >> 5;
    if (j == YD) {
        if (blockIdx.y == 0) g_T[tid * 8 + YD] = 0.f;
        if (blockIdx.y == 1) g_T[(tid + 64) * 8 + YD] = 0.f;  // covered below too
        // cover all 256 rows across 4 blocks
        g_T[(blockIdx.y * 64 + (tid & 63)) * 8 + YD] = 0.f;
        return;
    }
    wk[tid] = Wk[j * DD + tid];
    __syncthreads();
    const int sbase = blockIdx.y * 64;
    for (int s0 = 0; s0 < 64; s0 += 8) {
        int s = sbase + s0 + wid;
        float sum = 0.f;
        #pragma unroll
        for (int t = 0; t < 8; t++)
            sum += Wq[s * DD + lane + 32 * t] * wk[lane + 32 * t];
        #pragma unroll
        for (int o = 16; o; o >>= 1) sum += __shfl_xor_sync(0xffffffffu, sum, o);
        if (lane == 0) g_T[s * 8 + j] = sum * (0.0625f * LOG2E);
    }
}

// ---------------- kmain: fused low-rank attention ----------------
// grid = 256 CTAs (64 query rows each), 256 threads (8 warps).
// Warp w: row group rg = w&3 (16 rows), key group kg = w>>2 (64 of 128 keys/tile).
__global__ __launch_bounds__(256) void kmain(
    const float* __restrict__ x, const float* __restrict__ y,
    const float* __restrict__ Wv, float* __restrict__ out)
{
    __shared__ float Ts[DD][8];
    __shared__ float Us[64][9];
    __shared__ __align__(16) uint32_t ys2[2][128 * 10];  // tf32 y', j interleaved
    __shared__ __align__(16) uint32_t ysT[2][8 * 66];    // bf16 y'^T, interleaved
    __shared__ float Wvs[8][264];                        // Wv padded (row 7 = 0)
    __shared__ float wgt[4][16][8];

    const int tid = threadIdx.x, w = tid >> 5, lane = tid & 31;
    const int g = lane >> 2, tg = lane & 3;
    const int rg = w & 3, kg = w >> 2;
    const int qb = blockIdx.x * 64;

    // ---- load T and Wv ----
    for (int i = tid; i < DD * 8; i += 256) ((float*)Ts)[i] = g_T[i];
    for (int i = tid; i < 8 * DD; i += 256) {
        int j = i >> 8, c = i & 255;
        Wvs[j][c] = (j < YD) ? Wv[j * DD + c] : 0.f;
    }
    __syncthreads();

    // ---- Phase A: U = x_tile @ T (4 threads per row, quad shfl reduce) ----
    {
        const int r = tid >> 2, h = tid & 3;
        float acc[8];
        #pragma unroll
        for (int j = 0; j < 8; j++) acc[j] = 0.f;
        const float* xr = x + (size_t)(qb + r) * DD + h * 64;
        const float* tb = &Ts[h * 64][0];
        for (int k = 0; k < 64; k += 4) {
            float4 xv = *(const float4*)(xr + k);
            const float* t0 = tb + (k + 0) * 8;
            const float* t1 = tb + (k + 1) * 8;
            const float* t2 = tb + (k + 2) * 8;
            const float* t3 = tb + (k + 3) * 8;
            #pragma unroll
            for (int j = 0; j < 8; j++)
                acc[j] += xv.x * t0[j] + xv.y * t1[j] + xv.z * t2[j] + xv.w * t3[j];
        }
        #pragma unroll
        for (int j = 0; j < 8; j++) {
            acc[j] += __shfl_xor_sync(0xffffffffu, acc[j], 1);
            acc[j] += __shfl_xor_sync(0xffffffffu, acc[j], 2);
        }
        if (h == 0) {
            #pragma unroll
            for (int j = 0; j < 8; j++) Us[r][j] = acc[j];
        }
        __syncthreads();
    }

    // ---- per-warp tf32 A-fragment of U (K=8, persistent) ----
    uint32_t ua[4];
    {
        const int r0 = rg * 16 + g;
        ua[0] = to_tf32(Us[r0][tg]);
        ua[1] = to_tf32(Us[r0 + 8][tg]);
        ua[2] = to_tf32(Us[r0][tg + 4]);
        ua[3] = to_tf32(Us[r0 + 8][tg + 4]);
    }

    float eE0[4] = {0.f, 0.f, 0.f, 0.f}, eE1[4] = {0.f, 0.f, 0.f, 0.f};
    float eG0[4] = {0.f, 0.f, 0.f, 0.f}, eG1[4] = {0.f, 0.f, 0.f, 0.f};

    // ---- y' tile loader (cooperative, double-buffered) ----
    auto load_ys = [&](int tile, int buf) {
        const int mb = tile * 128;
        #pragma unroll
        for (int ii = 0; ii < 4; ii++) {
            int i = tid + ii * 256;            // 1024 entries
            int r = i >> 3, j = i & 7;
            float v = (j < YD) ? y[(size_t)(mb + r) * YD + j] : 1.0f;
            int jp = 2 * (j & 3) + (j >> 2);               // pair interleave
            ys2[buf][r * 10 + jp] = to_tf32(v);
            uint32_t wi = (uint32_t)(r >> 1);
            uint32_t t8 = wi & 7u;
            uint32_t np = (wi & ~7u) | (2u * (t8 & 3u) + (t8 >> 2));
            __nv_bfloat16* p = (__nv_bfloat16*)&ysT[buf][j * 66 + np];
            p[r & 1] = __float2bfloat16(v);
        }
    };

    load_ys(0, 0);

    // ---- main loop over 32 key tiles; warp handles kk = kg*4 .. kg*4+3 ----
    for (int t = 0; t < 32; t++) {
        const int buf = t & 1;
        __syncthreads();
        if (t < 31) load_ys(t + 1, buf ^ 1);

        const uint32_t* ysb = ys2[buf];
        const uint32_t* yT  = ysT[buf];

        #pragma unroll
        for (int kk = 0; kk < 4; kk++) {
            const int KK = kg * 4 + kk;
            uint32_t ae[4], ag[4];
            #pragma unroll
            for (int half = 0; half < 2; half++) {
                const int nt = KK * 2 + half;
                uint2 bb = *(const uint2*)&ysb[((nt * 8 + g) * 10) + 2 * tg];
                float c[4] = {0.f, 0.f, 0.f, 0.f};
                mma_tf32(c, ua, bb.x, bb.y);         // c = s * log2e
                float e0 = ex2f(c[0]), e1 = ex2f(c[1]);
                float e2 = ex2f(c[2]), e3 = ex2f(c[3]);
                ae[half * 2 + 0] = pack_bf16x2(e0, e1);
                ae[half * 2 + 1] = pack_bf16x2(e2, e3);
                ag[half * 2 + 0] = bmax0(pack_bf16x2(c[0], c[1]));
                ag[half * 2 + 1] = bmax0(pack_bf16x2(c[2], c[3]));
            }
            uint2 vb = *(const uint2*)&yT[g * 66 + KK * 8 + 2 * tg];
            if (kk & 1) {
                mma_bf16(eE1, ae, vb.x, vb.y);
                mma_bf16(eG1, ag, vb.x, vb.y);
            } else {
                mma_bf16(eE0, ae, vb.x, vb.y);
                mma_bf16(eG0, ag, vb.x, vb.y);
            }
        }
    }
    float eE[4], eG[4];
    #pragma unroll
    for (int i = 0; i < 4; i++) { eE[i] = eE0[i] + eE1[i]; eG[i] = eG0[i] + eG1[i]; }

    // ---- combine the two key groups via smem (aliased onto ys2[0]) ----
    float* pE = (float*)&ys2[0][0];            // [4][16][8] = 512 floats
    float* pG = pE + 512;
    __syncthreads();
    if (kg == 1) {
        pE[(rg * 16 + g) * 8 + 2 * tg]           = eE[0];
        pE[(rg * 16 + g) * 8 + 2 * tg + 1]       = eE[1];
        pE[(rg * 16 + g + 8) * 8 + 2 * tg]       = eE[2];
        pE[(rg * 16 + g + 8) * 8 + 2 * tg + 1]   = eE[3];
        pG[(rg * 16 + g) * 8 + 2 * tg]           = eG[0];
        pG[(rg * 16 + g) * 8 + 2 * tg + 1]       = eG[1];
        pG[(rg * 16 + g + 8) * 8 + 2 * tg]       = eG[2];
        pG[(rg * 16 + g + 8) * 8 + 2 * tg + 1]   = eG[3];
    }
    __syncthreads();
    if (kg == 0) {
        eE[0] += pE[(rg * 16 + g) * 8 + 2 * tg];
        eE[1] += pE[(rg * 16 + g) * 8 + 2 * tg + 1];
        eE[2] += pE[(rg * 16 + g + 8) * 8 + 2 * tg];
        eE[3] += pE[(rg * 16 + g + 8) * 8 + 2 * tg + 1];
        eG[0] += pG[(rg * 16 + g) * 8 + 2 * tg];
        eG[1] += pG[(rg * 16 + g) * 8 + 2 * tg + 1];
        eG[2] += pG[(rg * 16 + g + 8) * 8 + 2 * tg];
        eG[3] += pG[(rg * 16 + g + 8) * 8 + 2 * tg + 1];

        // per-row coefficients (Z, R_c in column 7 => quad lane tg==3)
        const int src = (lane & ~3) | 3;
        float Z0 = __shfl_sync(0xffffffffu, eE[1], src);
        float Z1 = __shfl_sync(0xffffffffu, eE[3], src);
        float R0 = __shfl_sync(0xffffffffu, eG[1], src);
        float R1 = __shfl_sync(0xffffffffu, eG[3], src);
        const float LN2_10 = 0.06931471805599453f;       // 0.1 * ln2
        float inv0 = 1.f / (LN2_10 * R0 + 1.f);
        float inv1 = 1.f / (LN2_10 * R1 + 1.f);
        float cA0 = LN2_10 * inv0, cB0 = inv0 / Z0;
        float cA1 = LN2_10 * inv1, cB1 = inv1 / Z1;

        wgt[rg][g][2 * tg]         = cA0 * eG[0] + cB0 * eE[0];
        wgt[rg][g][2 * tg + 1]     = cA0 * eG[1] + cB0 * eE[1];  // col7 garbage; Wvs row7=0
        wgt[rg][g + 8][2 * tg]     = cA1 * eG[2] + cB1 * eE[2];
        wgt[rg][g + 8][2 * tg + 1] = cA1 * eG[3] + cB1 * eE[3];
    }
    __syncthreads();

    // ---- out = wgt @ Wv: warp w handles 8 rows, lane owns 8 cols ----
    const int c0 = lane * 8;
    float wv[8][8];
    #pragma unroll
    for (int j = 0; j < 8; j++) {
        float4 v0 = *(const float4*)&Wvs[j][c0];
        float4 v1 = *(const float4*)&Wvs[j][c0 + 4];
        wv[j][0] = v0.x; wv[j][1] = v0.y; wv[j][2] = v0.z; wv[j][3] = v0.w;
        wv[j][4] = v1.x; wv[j][5] = v1.y; wv[j][6] = v1.z; wv[j][7] = v1.w;
    }
    #pragma unroll
    for (int rr = 0; rr < 8; rr++) {
        const int row = w * 8 + rr;
        float wj[8];
        #pragma unroll
        for (int j = 0; j < 8; j++) wj[j] = wgt[row >> 4][row & 15][j];
        float acc[8];
        #pragma unroll
        for (int c = 0; c < 8; c++) acc[c] = 0.f;
        #pragma unroll
        for (int j = 0; j < 8; j++)
            #pragma unroll
            for (int c = 0; c < 8; c++) acc[c] += wj[j] * wv[j][c];
        float* orow = out + (size_t)(qb + row) * DD + c0;
        *(float4*)(orow)     = make_float4(acc[0], acc[1], acc[2], acc[3]);
        *(float4*)(orow + 4) = make_float4(acc[4], acc[5], acc[6], acc[7]);
    }
}

// ---------------- launcher ----------------
extern "C" void kernel_launch(void* const* d_in, const int* in_sizes, int n_in,
                              void* d_out, int out_size) {
    const float* x  = (const float*)d_in[0];   // [16384, 256]
    const float* y  = (const float*)d_in[1];   // [4096, 7]
    const float* Wq = (const float*)d_in[2];   // [256, 256]
    const float* Wk = (const float*)d_in[3];   // [7, 256]
    const float* Wv = (const float*)d_in[4];   // [7, 256]
    float* out = (float*)d_out;                // [16384, 256]

    k0a<<<dim3(8, 4), 256>>>(Wq, Wk);
    kmain<<<N_Q / 64, 256>>>(x, y, Wv, out);
}

// round 13
// speedup vs baseline: 14.2143x; 1.0221x over previous
#include <cuda_runtime.h>
#include <cuda_fp16.h>
#include <cstdint>

#define N_Q 16384
#define M_K 4096
#define DD  256
#define YD  7
#define LOG2E 1.4426950408889634f

// T[s][j] = (Wq @ Wk^T)[s][j] * (log2e/16), col 7 = 0
__device__ float g_T[DD * 8];
// pre-formatted y' tiles: exact smem images
__device__ uint32_t g_ys2t[32 * 1280];   // tf32, [tile][r*10 + jp]
__device__ uint32_t g_ysTt[32 * 528];    // f16x2, [tile][j*66 + np] (pair r&1)

// ---------------- helpers ----------------
__device__ __forceinline__ uint32_t to_tf32(float x) {
    uint32_t u;
    asm("cvt.rna.tf32.f32 %0, %1;" : "=r"(u) : "f"(x));
    return u;
}
__device__ __forceinline__ uint32_t pack_f16x2(float lo, float hi) {
    uint32_t r;
    asm("cvt.rn.f16x2.f32 %0, %1, %2;" : "=r"(r) : "f"(hi), "f"(lo));
    return r;
}
__device__ __forceinline__ uint32_t hmax0(uint32_t v) {
    uint32_t r;
    asm("max.f16x2 %0, %1, %2;" : "=r"(r) : "r"(v), "r"(0u));
    return r;
}
__device__ __forceinline__ uint32_t hex2(uint32_t v) {
    uint32_t r;
    asm("ex2.approx.f16x2 %0, %1;" : "=r"(r) : "r"(v));
    return r;
}
__device__ __forceinline__ void mma_tf32(float* c, const uint32_t* a,
                                         uint32_t b0, uint32_t b1) {
    asm volatile(
        "mma.sync.aligned.m16n8k8.row.col.f32.tf32.tf32.f32 "
        "{%0,%1,%2,%3}, {%4,%5,%6,%7}, {%8,%9}, {%0,%1,%2,%3};"
        : "+f"(c[0]), "+f"(c[1]), "+f"(c[2]), "+f"(c[3])
        : "r"(a[0]), "r"(a[1]), "r"(a[2]), "r"(a[3]), "r"(b0), "r"(b1));
}
__device__ __forceinline__ void mma_f16(float* c, const uint32_t* a,
                                        uint32_t b0, uint32_t b1) {
    asm volatile(
        "mma.sync.aligned.m16n8k16.row.col.f32.f16.f16.f32 "
        "{%0,%1,%2,%3}, {%4,%5,%6,%7}, {%8,%9}, {%0,%1,%2,%3};"
        : "+f"(c[0]), "+f"(c[1]), "+f"(c[2]), "+f"(c[3])
        : "r"(a[0]), "r"(a[1]), "r"(a[2]), "r"(a[3]), "r"(b0), "r"(b1));
}

// ---------------- kprep: T matrix + y' tile formatting ----------------
// grid 64: blocks 0..31 compute T (j = b&7, s-chunk = b>>3),
//          blocks 32..63 format y' tile (b-32).
__global__ void kprep(const float* __restrict__ Wq, const float* __restrict__ Wk,
                      const float* __restrict__ y) {
    const int b = blockIdx.x;
    const int tid = threadIdx.x;
    if (b < 32) {
        const int j = b & 7, sbase = (b >> 3) * 64;
        const int lane = tid & 31, wid = tid >> 5;
        __shared__ float wk[DD];
        if (j == YD) {
            g_T[(sbase + (tid & 63)) * 8 + YD] = 0.f;
            return;
        }
        wk[tid] = Wk[j * DD + tid];
        __syncthreads();
        for (int s0 = 0; s0 < 64; s0 += 8) {
            int s = sbase + s0 + wid;
            float sum = 0.f;
            #pragma unroll
            for (int t = 0; t < 8; t++)
                sum += Wq[s * DD + lane + 32 * t] * wk[lane + 32 * t];
            #pragma unroll
            for (int o = 16; o; o >>= 1) sum += __shfl_xor_sync(0xffffffffu, sum, o);
            if (lane == 0) g_T[s * 8 + j] = sum * (0.0625f * LOG2E);
        }
    } else {
        const int tile = b - 32;
        #pragma unroll
        for (int ii = 0; ii < 4; ii++) {
            int i = tid + ii * 256;            // 1024 entries
            int r = i >> 3, j = i & 7;
            float v = (j < YD) ? y[(size_t)(tile * 128 + r) * YD + j] : 1.0f;
            int jp = 2 * (j & 3) + (j >> 2);
            g_ys2t[tile * 1280 + r * 10 + jp] = to_tf32(v);
            uint32_t wi = (uint32_t)(r >> 1), t8 = wi & 7u;
            uint32_t np = (wi & ~7u) | (2u * (t8 & 3u) + (t8 >> 2));
            ((__half*)g_ysTt)[(size_t)tile * 1056 + (j * 66 + np) * 2 + (r & 1)] =
                __float2half(v);
        }
    }
}

// ---------------- kmain: fused low-rank attention ----------------
// grid = 256 CTAs (64 query rows each), 256 threads (8 warps).
// Warp w: row group rg = w&3 (16 rows), key group kg = w>>2 (64 of 128 keys/tile).
__global__ __launch_bounds__(256) void kmain(
    const float* __restrict__ x, const float* __restrict__ Wv,
    float* __restrict__ out)
{
    __shared__ float Ts[DD][8];
    __shared__ float Us[64][9];
    __shared__ __align__(16) uint32_t ys2[2][1280];  // tf32 y', j interleaved
    __shared__ __align__(16) uint32_t ysT[2][528];   // f16 y'^T, interleaved
    __shared__ float Wvs[8][264];                    // Wv padded (row 7 = 0)
    __shared__ float wgt[4][16][8];

    const int tid = threadIdx.x, w = tid >> 5, lane = tid & 31;
    const int g = lane >> 2, tg = lane & 3;
    const int rg = w & 3, kg = w >> 2;
    const int qb = blockIdx.x * 64;

    // ---- load T and Wv ----
    for (int i = tid; i < DD * 8; i += 256) ((float*)Ts)[i] = g_T[i];
    for (int i = tid; i < 8 * DD; i += 256) {
        int j = i >> 8, c = i & 255;
        Wvs[j][c] = (j < YD) ? Wv[j * DD + c] : 0.f;
    }
    __syncthreads();

    // ---- Phase A: U = x_tile @ T (4 threads per row, quad shfl reduce) ----
    {
        const int r = tid >> 2, h = tid & 3;
        float acc[8];
        #pragma unroll
        for (int j = 0; j < 8; j++) acc[j] = 0.f;
        const float* xr = x + (size_t)(qb + r) * DD + h * 64;
        const float* tb = &Ts[h * 64][0];
        for (int k = 0; k < 64; k += 4) {
            float4 xv = *(const float4*)(xr + k);
            const float* t0 = tb + (k + 0) * 8;
            const float* t1 = tb + (k + 1) * 8;
            const float* t2 = tb + (k + 2) * 8;
            const float* t3 = tb + (k + 3) * 8;
            #pragma unroll
            for (int j = 0; j < 8; j++)
                acc[j] += xv.x * t0[j] + xv.y * t1[j] + xv.z * t2[j] + xv.w * t3[j];
        }
        #pragma unroll
        for (int j = 0; j < 8; j++) {
            acc[j] += __shfl_xor_sync(0xffffffffu, acc[j], 1);
            acc[j] += __shfl_xor_sync(0xffffffffu, acc[j], 2);
        }
        if (h == 0) {
            #pragma unroll
            for (int j = 0; j < 8; j++) Us[r][j] = acc[j];
        }
        __syncthreads();
    }

    // ---- per-warp tf32 A-fragment of U (K=8, persistent) ----
    uint32_t ua[4];
    {
        const int r0 = rg * 16 + g;
        ua[0] = to_tf32(Us[r0][tg]);
        ua[1] = to_tf32(Us[r0 + 8][tg]);
        ua[2] = to_tf32(Us[r0][tg + 4]);
        ua[3] = to_tf32(Us[r0 + 8][tg + 4]);
    }

    float eE0[4] = {0.f, 0.f, 0.f, 0.f}, eE1[4] = {0.f, 0.f, 0.f, 0.f};
    float eG0[4] = {0.f, 0.f, 0.f, 0.f}, eG1[4] = {0.f, 0.f, 0.f, 0.f};

    // ---- y' tile loader: pure coalesced copies of pre-baked images ----
    auto load_ys = [&](int tile, int buf) {
        const float4* s2 = (const float4*)&g_ys2t[tile * 1280];
        float4* d2 = (float4*)&ys2[buf][0];
        #pragma unroll
        for (int i = tid; i < 320; i += 256) d2[i] = s2[i];
        const float4* sT = (const float4*)&g_ysTt[tile * 528];
        float4* dT = (float4*)&ysT[buf][0];
        if (tid < 132) dT[tid] = sT[tid];
    };

    load_ys(0, 0);

    // ---- main loop over 32 key tiles; warp handles kk = kg*4 .. kg*4+3 ----
    for (int t = 0; t < 32; t++) {
        const int buf = t & 1;
        __syncthreads();
        if (t < 31) load_ys(t + 1, buf ^ 1);

        const uint32_t* ysb = ys2[buf];
        const uint32_t* yT  = ysT[buf];

        #pragma unroll
        for (int kk = 0; kk < 4; kk++) {
            const int KK = kg * 4 + kk;
            uint32_t ae[4], ag[4];
            #pragma unroll
            for (int half = 0; half < 2; half++) {
                const int nt = KK * 2 + half;
                uint2 bb = *(const uint2*)&ysb[((nt * 8 + g) * 10) + 2 * tg];
                float c[4] = {0.f, 0.f, 0.f, 0.f};
                mma_tf32(c, ua, bb.x, bb.y);         // c = s * log2e
                uint32_t p01 = pack_f16x2(c[0], c[1]);
                uint32_t p23 = pack_f16x2(c[2], c[3]);
                ag[half * 2 + 0] = hmax0(p01);       // relu (log2-scaled)
                ag[half * 2 + 1] = hmax0(p23);
                ae[half * 2 + 0] = hex2(p01);        // exp2 -> A fragment
                ae[half * 2 + 1] = hex2(p23);
            }
            uint2 vb = *(const uint2*)&yT[g * 66 + KK * 8 + 2 * tg];
            if (kk & 1) {
                mma_f16(eG1, ag, vb.x, vb.y);
                mma_f16(eE1, ae, vb.x, vb.y);
            } else {
                mma_f16(eG0, ag, vb.x, vb.y);
                mma_f16(eE0, ae, vb.x, vb.y);
            }
        }
    }
    float eE[4], eG[4];
    #pragma unroll
    for (int i = 0; i < 4; i++) { eE[i] = eE0[i] + eE1[i]; eG[i] = eG0[i] + eG1[i]; }

    // ---- combine the two key groups via smem (aliased onto ys2[0]) ----
    float* pE = (float*)&ys2[0][0];            // [4][16][8] = 512 floats
    float* pG = pE + 512;
    __syncthreads();
    if (kg == 1) {
        pE[(rg * 16 + g) * 8 + 2 * tg]           = eE[0];
        pE[(rg * 16 + g) * 8 + 2 * tg + 1]       = eE[1];
        pE[(rg * 16 + g + 8) * 8 + 2 * tg]       = eE[2];
        pE[(rg * 16 + g + 8) * 8 + 2 * tg + 1]   = eE[3];
        pG[(rg * 16 + g) * 8 + 2 * tg]           = eG[0];
        pG[(rg * 16 + g) * 8 + 2 * tg + 1]       = eG[1];
        pG[(rg * 16 + g + 8) * 8 + 2 * tg]       = eG[2];
        pG[(rg * 16 + g + 8) * 8 + 2 * tg + 1]   = eG[3];
    }
    __syncthreads();
    if (kg == 0) {
        eE[0] += pE[(rg * 16 + g) * 8 + 2 * tg];
        eE[1] += pE[(rg * 16 + g) * 8 + 2 * tg + 1];
        eE[2] += pE[(rg * 16 + g + 8) * 8 + 2 * tg];
        eE[3] += pE[(rg * 16 + g + 8) * 8 + 2 * tg + 1];
        eG[0] += pG[(rg * 16 + g) * 8 + 2 * tg];
        eG[1] += pG[(rg * 16 + g) * 8 + 2 * tg + 1];
        eG[2] += pG[(rg * 16 + g + 8) * 8 + 2 * tg];
        eG[3] += pG[(rg * 16 + g + 8) * 8 + 2 * tg + 1];

        // per-row coefficients (Z, R_c in column 7 => quad lane tg==3)
        const int src = (lane & ~3) | 3;
        float Z0 = __shfl_sync(0xffffffffu, eE[1], src);
        float Z1 = __shfl_sync(0xffffffffu, eE[3], src);
        float R0 = __shfl_sync(0xffffffffu, eG[1], src);
        float R1 = __shfl_sync(0xffffffffu, eG[3], src);
        const float LN2_10 = 0.06931471805599453f;       // 0.1 * ln2
        float inv0 = 1.f / (LN2_10 * R0 + 1.f);
        float inv1 = 1.f / (LN2_10 * R1 + 1.f);
        float cA0 = LN2_10 * inv0, cB0 = inv0 / Z0;
        float cA1 = LN2_10 * inv1, cB1 = inv1 / Z1;

        wgt[rg][g][2 * tg]         = cA0 * eG[0] + cB0 * eE[0];
        wgt[rg][g][2 * tg + 1]     = cA0 * eG[1] + cB0 * eE[1];  // col7 garbage; Wvs row7=0
        wgt[rg][g + 8][2 * tg]     = cA1 * eG[2] + cB1 * eE[2];
        wgt[rg][g + 8][2 * tg + 1] = cA1 * eG[3] + cB1 * eE[3];
    }
    __syncthreads();

    // ---- out = wgt @ Wv: warp w handles 8 rows, lane owns 8 cols ----
    const int c0 = lane * 8;
    float wv[8][8];
    #pragma unroll
    for (int j = 0; j < 8; j++) {
        float4 v0 = *(const float4*)&Wvs[j][c0];
        float4 v1 = *(const float4*)&Wvs[j][c0 + 4];
        wv[j][0] = v0.x; wv[j][1] = v0.y; wv[j][2] = v0.z; wv[j][3] = v0.w;
        wv[j][4] = v1.x; wv[j][5] = v1.y; wv[j][6] = v1.z; wv[j][7] = v1.w;
    }
    #pragma unroll
    for (int rr = 0; rr < 8; rr++) {
        const int row = w * 8 + rr;
        float wj[8];
        #pragma unroll
        for (int j = 0; j < 8; j++) wj[j] = wgt[row >> 4][row & 15][j];
        float acc[8];
        #pragma unroll
        for (int c = 0; c < 8; c++) acc[c] = 0.f;
        #pragma unroll
        for (int j = 0; j < 8; j++)
            #pragma unroll
            for (int c = 0; c < 8; c++) acc[c] += wj[j] * wv[j][c];
        float* orow = out + (size_t)(qb + row) * DD + c0;
        *(float4*)(orow)     = make_float4(acc[0], acc[1], acc[2], acc[3]);
        *(float4*)(orow + 4) = make_float4(acc[4], acc[5], acc[6], acc[7]);
    }
}

// ---------------- launcher ----------------
extern "C" void kernel_launch(void* const* d_in, const int* in_sizes, int n_in,
                              void* d_out, int out_size) {
    const float* x  = (const float*)d_in[0];   // [16384, 256]
    const float* y  = (const float*)d_in[1];   // [4096, 7]
    const float* Wq = (const float*)d_in[2];   // [256, 256]
    const float* Wk = (const float*)d_in[3];   // [7, 256]
    const float* Wv = (const float*)d_in[4];   // [7, 256]
    float* out = (float*)d_out;                // [16384, 256]

    kprep<<<64, 256>>>(Wq, Wk, y);
    kmain<<<N_Q / 64, 256>>>(x, Wv, out);
}

// round 15
// speedup vs baseline: 16.1106x; 1.1334x over previous
#include <cuda_runtime.h>
#include <cuda_fp16.h>
#include <cstdint>

#define N_Q 16384
#define M_K 4096
#define DD  256
#define YD  7
#define LOG2E 1.4426950408889634f

// T[s][j] = (Wq @ Wk^T)[s][j] * (log2e/16), col 7 = 0
__device__ float g_T[DD * 8];
// pre-baked per-tile fragment images: [tile][1536 words]
//   words 0..1023:  ys2f4[KK][lane] uint4  (tf32 B-frags, nt=2KK & 2KK+1)
//   words 1024..1535: yTf[KK][lane] uint2  (f16 B-frag for key block KK)
__device__ uint32_t g_frag[32 * 1536];

// ---------------- helpers ----------------
__device__ __forceinline__ uint32_t to_tf32(float x) {
    uint32_t u;
    asm("cvt.rna.tf32.f32 %0, %1;" : "=r"(u) : "f"(x));
    return u;
}
__device__ __forceinline__ uint32_t pack_f16x2(float lo, float hi) {
    uint32_t r;
    asm("cvt.rn.f16x2.f32 %0, %1, %2;" : "=r"(r) : "f"(hi), "f"(lo));
    return r;
}
__device__ __forceinline__ uint32_t hmax0(uint32_t v) {
    uint32_t r;
    asm("max.f16x2 %0, %1, %2;" : "=r"(r) : "r"(v), "r"(0u));
    return r;
}
__device__ __forceinline__ uint32_t hex2(uint32_t v) {
    uint32_t r;
    asm("ex2.approx.f16x2 %0, %1;" : "=r"(r) : "r"(v));
    return r;
}
__device__ __forceinline__ void mma_tf32(float* c, const uint32_t* a,
                                         uint32_t b0, uint32_t b1) {
    asm volatile(
        "mma.sync.aligned.m16n8k8.row.col.f32.tf32.tf32.f32 "
        "{%0,%1,%2,%3}, {%4,%5,%6,%7}, {%8,%9}, {%0,%1,%2,%3};"
        : "+f"(c[0]), "+f"(c[1]), "+f"(c[2]), "+f"(c[3])
        : "r"(a[0]), "r"(a[1]), "r"(a[2]), "r"(a[3]), "r"(b0), "r"(b1));
}
__device__ __forceinline__ void mma_f16(float* c, const uint32_t* a,
                                        uint32_t b0, uint32_t b1) {
    asm volatile(
        "mma.sync.aligned.m16n8k16.row.col.f32.f16.f16.f32 "
        "{%0,%1,%2,%3}, {%4,%5,%6,%7}, {%8,%9}, {%0,%1,%2,%3};"
        : "+f"(c[0]), "+f"(c[1]), "+f"(c[2]), "+f"(c[3])
        : "r"(a[0]), "r"(a[1]), "r"(a[2]), "r"(a[3]), "r"(b0), "r"(b1));
}

// ---------------- kprep: T matrix + fragment baking ----------------
// grid 64: blocks 0..31 compute T (j = b&7, s-chunk = b>>3),
//          blocks 32..63 bake fragments for tile (b-32).
__global__ void kprep(const float* __restrict__ Wq, const float* __restrict__ Wk,
                      const float* __restrict__ y) {
    const int b = blockIdx.x;
    const int tid = threadIdx.x;
    if (b < 32) {
        const int j = b & 7, sbase = (b >> 3) * 64;
        const int lane = tid & 31, wid = tid >> 5;
        __shared__ float wk[DD];
        if (j == YD) {
            g_T[(sbase + (tid & 63)) * 8 + YD] = 0.f;
            return;
        }
        wk[tid] = Wk[j * DD + tid];
        __syncthreads();
        for (int s0 = 0; s0 < 64; s0 += 8) {
            int s = sbase + s0 + wid;
            float sum = 0.f;
            #pragma unroll
            for (int t = 0; t < 8; t++)
                sum += Wq[s * DD + lane + 32 * t] * wk[lane + 32 * t];
            #pragma unroll
            for (int o = 16; o; o >>= 1) sum += __shfl_xor_sync(0xffffffffu, sum, o);
            if (lane == 0) g_T[s * 8 + j] = sum * (0.0625f * LOG2E);
        }
    } else {
        const int tile = b - 32;
        const int KK = tid >> 5, lane = tid & 31;
        const int g = lane >> 2, tg = lane & 3;
        auto yv = [&](int r, int j) -> float {
            return (j < YD) ? y[(size_t)(tile * 128 + r) * YD + j] : 1.0f;
        };
        // tf32 B-fragments: half0 keys KK*16+g, half1 keys KK*16+8+g; j = tg, tg+4
        uint32_t* dst = &g_frag[tile * 1536];
        uint4 v4;
        v4.x = to_tf32(yv(KK * 16 + g, tg));
        v4.y = to_tf32(yv(KK * 16 + g, tg + 4));
        v4.z = to_tf32(yv(KK * 16 + 8 + g, tg));
        v4.w = to_tf32(yv(KK * 16 + 8 + g, tg + 4));
        *(uint4*)&dst[(KK * 32 + lane) * 4] = v4;
        // f16 B-fragment: b0 = keys KK*16+2tg,+1 at j=g; b1 = keys KK*16+8+2tg,+9
        uint2 v2;
        v2.x = pack_f16x2(yv(KK * 16 + 2 * tg, g),     yv(KK * 16 + 2 * tg + 1, g));
        v2.y = pack_f16x2(yv(KK * 16 + 8 + 2 * tg, g), yv(KK * 16 + 9 + 2 * tg, g));
        *(uint2*)&dst[1024 + (KK * 32 + lane) * 2] = v2;
    }
}

// ---------------- kmain: fused low-rank attention ----------------
// grid = 256 CTAs (64 query rows each), 256 threads (8 warps).
// Warp w: row group rg = w&3 (16 rows), key group kg = w>>2 (64 of 128 keys/tile).
__global__ __launch_bounds__(256) void kmain(
    const float* __restrict__ x, const float* __restrict__ Wv,
    float* __restrict__ out)
{
    __shared__ float Ts[DD][8];
    __shared__ float Us[64][9];
    __shared__ __align__(16) uint32_t frag[2][1536];  // fragment images
    __shared__ float Wvs[8][264];                     // Wv padded (row 7 = 0)
    __shared__ float wgt[4][16][8];

    const int tid = threadIdx.x, w = tid >> 5, lane = tid & 31;
    const int g = lane >> 2, tg = lane & 3;
    const int rg = w & 3, kg = w >> 2;
    const int qb = blockIdx.x * 64;

    // ---- load T and Wv ----
    for (int i = tid; i < DD * 8; i += 256) ((float*)Ts)[i] = g_T[i];
    for (int i = tid; i < 8 * DD; i += 256) {
        int j = i >> 8, c = i & 255;
        Wvs[j][c] = (j < YD) ? Wv[j * DD + c] : 0.f;
    }
    __syncthreads();

    // ---- Phase A: U = x_tile @ T (4 threads per row, quad shfl reduce) ----
    {
        const int r = tid >> 2, h = tid & 3;
        float acc[8];
        #pragma unroll
        for (int j = 0; j < 8; j++) acc[j] = 0.f;
        const float* xr = x + (size_t)(qb + r) * DD + h * 64;
        const float* tb = &Ts[h * 64][0];
        for (int k = 0; k < 64; k += 4) {
            float4 xv = *(const float4*)(xr + k);
            const float* t0 = tb + (k + 0) * 8;
            const float* t1 = tb + (k + 1) * 8;
            const float* t2 = tb + (k + 2) * 8;
            const float* t3 = tb + (k + 3) * 8;
            #pragma unroll
            for (int j = 0; j < 8; j++)
                acc[j] += xv.x * t0[j] + xv.y * t1[j] + xv.z * t2[j] + xv.w * t3[j];
        }
        #pragma unroll
        for (int j = 0; j < 8; j++) {
            acc[j] += __shfl_xor_sync(0xffffffffu, acc[j], 1);
            acc[j] += __shfl_xor_sync(0xffffffffu, acc[j], 2);
        }
        if (h == 0) {
            #pragma unroll
            for (int j = 0; j < 8; j++) Us[r][j] = acc[j];
        }
        __syncthreads();
    }

    // ---- per-warp tf32 A-fragment of U (K=8, persistent) ----
    uint32_t ua[4];
    {
        const int r0 = rg * 16 + g;
        ua[0] = to_tf32(Us[r0][tg]);
        ua[1] = to_tf32(Us[r0 + 8][tg]);
        ua[2] = to_tf32(Us[r0][tg + 4]);
        ua[3] = to_tf32(Us[r0 + 8][tg + 4]);
    }

    float eE0[4] = {0.f, 0.f, 0.f, 0.f}, eE1[4] = {0.f, 0.f, 0.f, 0.f};
    float eG0[4] = {0.f, 0.f, 0.f, 0.f}, eG1[4] = {0.f, 0.f, 0.f, 0.f};

    // ---- loader: coalesced copy of pre-baked fragment image ----
    auto load_frag = [&](int tile, int buf) {
        const float4* s = (const float4*)&g_frag[tile * 1536];
        float4* d = (float4*)&frag[buf][0];
        d[tid] = s[tid];                       // 256 of 384
        if (tid < 128) d[tid + 256] = s[tid + 256];
    };

    load_frag(0, 0);

    // ---- main loop over 32 key tiles; warp handles KK = kg*4 .. kg*4+3 ----
    for (int t = 0; t < 32; t++) {
        const int buf = t & 1;
        __syncthreads();
        if (t < 31) load_frag(t + 1, buf ^ 1);

        const uint32_t* fb = frag[buf];

        #pragma unroll
        for (int kk = 0; kk < 4; kk++) {
            const int KK = kg * 4 + kk;
            uint32_t ae[4], ag[4];
            uint4 bb = *(const uint4*)&fb[(KK * 32 + lane) * 4];   // LDS.128, 0-conflict
            {
                float c[4] = {0.f, 0.f, 0.f, 0.f};
                mma_tf32(c, ua, bb.x, bb.y);          // scores * log2e, keys KK*16..+7
                uint32_t p01 = pack_f16x2(c[0], c[1]);
                uint32_t p23 = pack_f16x2(c[2], c[3]);
                ag[0] = hmax0(p01);  ag[1] = hmax0(p23);
                ae[0] = hex2(p01);   ae[1] = hex2(p23);
            }
            {
                float c[4] = {0.f, 0.f, 0.f, 0.f};
                mma_tf32(c, ua, bb.z, bb.w);          // keys KK*16+8..+15
                uint32_t p01 = pack_f16x2(c[0], c[1]);
                uint32_t p23 = pack_f16x2(c[2], c[3]);
                ag[2] = hmax0(p01);  ag[3] = hmax0(p23);
                ae[2] = hex2(p01);   ae[3] = hex2(p23);
            }
            uint2 vb = *(const uint2*)&fb[1024 + (KK * 32 + lane) * 2];  // LDS.64, 0-conflict
            if (kk & 1) {
                mma_f16(eG1, ag, vb.x, vb.y);
                mma_f16(eE1, ae, vb.x, vb.y);
            } else {
                mma_f16(eG0, ag, vb.x, vb.y);
                mma_f16(eE0, ae, vb.x, vb.y);
            }
        }
    }
    float eE[4], eG[4];
    #pragma unroll
    for (int i = 0; i < 4; i++) { eE[i] = eE0[i] + eE1[i]; eG[i] = eG0[i] + eG1[i]; }

    // ---- combine the two key groups via smem (aliased onto frag[0]) ----
    float* pE = (float*)&frag[0][0];           // [4][16][8] = 512 floats
    float* pG = pE + 512;
    __syncthreads();
    if (kg == 1) {
        pE[(rg * 16 + g) * 8 + 2 * tg]           = eE[0];
        pE[(rg * 16 + g) * 8 + 2 * tg + 1]       = eE[1];
        pE[(rg * 16 + g + 8) * 8 + 2 * tg]       = eE[2];
        pE[(rg * 16 + g + 8) * 8 + 2 * tg + 1]   = eE[3];
        pG[(rg * 16 + g) * 8 + 2 * tg]           = eG[0];
        pG[(rg * 16 + g) * 8 + 2 * tg + 1]       = eG[1];
        pG[(rg * 16 + g + 8) * 8 + 2 * tg]       = eG[2];
        pG[(rg * 16 + g + 8) * 8 + 2 * tg + 1]   = eG[3];
    }
    __syncthreads();
    if (kg == 0) {
        eE[0] += pE[(rg * 16 + g) * 8 + 2 * tg];
        eE[1] += pE[(rg * 16 + g) * 8 + 2 * tg + 1];
        eE[2] += pE[(rg * 16 + g + 8) * 8 + 2 * tg];
        eE[3] += pE[(rg * 16 + g + 8) * 8 + 2 * tg + 1];
        eG[0] += pG[(rg * 16 + g) * 8 + 2 * tg];
        eG[1] += pG[(rg * 16 + g) * 8 + 2 * tg + 1];
        eG[2] += pG[(rg * 16 + g + 8) * 8 + 2 * tg];
        eG[3] += pG[(rg * 16 + g + 8) * 8 + 2 * tg + 1];

        // per-row coefficients (Z, R_c in column 7 => quad lane tg==3)
        const int src = (lane & ~3) | 3;
        float Z0 = __shfl_sync(0xffffffffu, eE[1], src);
        float Z1 = __shfl_sync(0xffffffffu, eE[3], src);
        float R0 = __shfl_sync(0xffffffffu, eG[1], src);
        float R1 = __shfl_sync(0xffffffffu, eG[3], src);
        const float LN2_10 = 0.06931471805599453f;       // 0.1 * ln2
        float inv0 = 1.f / (LN2_10 * R0 + 1.f);
        float inv1 = 1.f / (LN2_10 * R1 + 1.f);
        float cA0 = LN2_10 * inv0, cB0 = inv0 / Z0;
        float cA1 = LN2_10 * inv1, cB1 = inv1 / Z1;

        wgt[rg][g][2 * tg]         = cA0 * eG[0] + cB0 * eE[0];
        wgt[rg][g][2 * tg + 1]     = cA0 * eG[1] + cB0 * eE[1];  // col7 garbage; Wvs row7=0
        wgt[rg][g + 8][2 * tg]     = cA1 * eG[2] + cB1 * eE[2];
        wgt[rg][g + 8][2 * tg + 1] = cA1 * eG[3] + cB1 * eE[3];
    }
    __syncthreads();

    // ---- out = wgt @ Wv: warp w handles 8 rows, lane owns 8 cols ----
    const int c0 = lane * 8;
    float wv[8][8];
    #pragma unroll
    for (int j = 0; j < 8; j++) {
        float4 v0 = *(const float4*)&Wvs[j][c0];
        float4 v1 = *(const float4*)&Wvs[j][c0 + 4];
        wv[j][0] = v0.x; wv[j][1] = v0.y; wv[j][2] = v0.z; wv[j][3] = v0.w;
        wv[j][4] = v1.x; wv[j][5] = v1.y; wv[j][6] = v1.z; wv[j][7] = v1.w;
    }
    #pragma unroll
    for (int rr = 0; rr < 8; rr++) {
        const int row = w * 8 + rr;
        float wj[8];
        #pragma unroll
        for (int j = 0; j < 8; j++) wj[j] = wgt[row >> 4][row & 15][j];
        float acc[8];
        #pragma unroll
        for (int c = 0; c < 8; c++) acc[c] = 0.f;
        #pragma unroll
        for (int j = 0; j < 8; j++)
            #pragma unroll
            for (int c = 0; c < 8; c++) acc[c] += wj[j] * wv[j][c];
        float* orow = out + (size_t)(qb + row) * DD + c0;
        *(float4*)(orow)     = make_float4(acc[0], acc[1], acc[2], acc[3]);
        *(float4*)(orow + 4) = make_float4(acc[4], acc[5], acc[6], acc[7]);
    }
}

// ---------------- launcher ----------------
extern "C" void kernel_launch(void* const* d_in, const int* in_sizes, int n_in,
                              void* d_out, int out_size) {
    const float* x  = (const float*)d_in[0];   // [16384, 256]
    const float* y  = (const float*)d_in[1];   // [4096, 7]
    const float* Wq = (const float*)d_in[2];   // [256, 256]
    const float* Wk = (const float*)d_in[3];   // [7, 256]
    const float* Wv = (const float*)d_in[4];   // [7, 256]
    float* out = (float*)d_out;                // [16384, 256]

    kprep<<<64, 256>>>(Wq, Wk, y);
    kmain<<<N_Q / 64, 256>>>(x, Wv, out);
}